// round 1
// baseline (speedup 1.0000x reference)
#include <cuda_runtime.h>

namespace {
constexpr int BATCH = 8;
constexpr int NA = 1024;     // 32*32 aim positions
constexpr int ND = 4096;     // 64*64 detect positions
constexpr int C  = 512;
constexpr int CI = 256;
constexpr int RA = BATCH * NA;   // 8192  flattened aim rows
constexpr int RD = BATCH * ND;   // 32768 flattened detect rows
constexpr float EPS = 1e-3f;
}

// Scratch (bss, allocation-free)
__device__ float g_dx[(long)RD * CI];      // detect @ Wg
__device__ float g_ax[(long)RA * CI];      // aim @ Wg
__device__ float g_th[(long)RA * CI];      // aim @ Wt
__device__ float g_ph[(long)RD * CI];      // detect @ Wp
__device__ float g_m1[(long)BATCH * CI * CI];  // phi^T @ dx / ND
__device__ float g_m2[(long)BATCH * CI * CI];  // th^T  @ ax / NA
__device__ float g_nap[(long)RA * CI];     // non_aim pre-conv
__device__ float g_ndp[(long)RD * CI];     // non_det pre-conv

// MODE: 0 = plain, 1 = +bias[col], 2 = *scale, 3 = BN(acc+bias)+resid
// TRANS_A: A stored as (K x M) row-major (i.e. compute A^T @ B)
template<int MODE, bool TRANS_A>
__global__ __launch_bounds__(256)
void gemm64(const float* __restrict__ A, const float* __restrict__ Bm,
            float* __restrict__ Cm,
            int M, int N, int K,
            long sA, long sB, long sC,
            const float* __restrict__ bias, float scale,
            const float* __restrict__ gam, const float* __restrict__ beta,
            const float* __restrict__ mean, const float* __restrict__ var,
            const float* __restrict__ resid)
{
    constexpr int BM = 64, BN = 64, BK = 16;
    __shared__ float As[BK][BM];
    __shared__ float Bs[BK][BN];

    const int tid = threadIdx.x;
    const int bz  = blockIdx.z;
    A  += (long)bz * sA;
    Bm += (long)bz * sB;
    Cm += (long)bz * sC;

    const int m0 = blockIdx.y * BM;
    const int n0 = blockIdx.x * BN;

    const int ty = tid >> 4;   // 0..15
    const int tx = tid & 15;   // 0..15

    float acc[4][4] = {};

    for (int k0 = 0; k0 < K; k0 += BK) {
        if (!TRANS_A) {
            // A is (M x K) row-major: load 4 consecutive K per thread, transpose into smem
            const int m  = tid >> 2;          // 0..63
            const int kq = (tid & 3) * 4;     // 0,4,8,12
            float4 v = *reinterpret_cast<const float4*>(&A[(long)(m0 + m) * K + k0 + kq]);
            As[kq + 0][m] = v.x; As[kq + 1][m] = v.y;
            As[kq + 2][m] = v.z; As[kq + 3][m] = v.w;
        } else {
            // A is (K x M) row-major: direct coalesced copy
            const int k  = tid >> 4;          // 0..15
            const int mq = (tid & 15) * 4;
            float4 v = *reinterpret_cast<const float4*>(&A[(long)(k0 + k) * M + m0 + mq]);
            As[k][mq + 0] = v.x; As[k][mq + 1] = v.y;
            As[k][mq + 2] = v.z; As[k][mq + 3] = v.w;
        }
        {
            const int k  = tid >> 4;
            const int nq = (tid & 15) * 4;
            float4 v = *reinterpret_cast<const float4*>(&Bm[(long)(k0 + k) * N + n0 + nq]);
            Bs[k][nq + 0] = v.x; Bs[k][nq + 1] = v.y;
            Bs[k][nq + 2] = v.z; Bs[k][nq + 3] = v.w;
        }
        __syncthreads();

        #pragma unroll
        for (int k = 0; k < BK; ++k) {
            float4 av = *reinterpret_cast<const float4*>(&As[k][ty * 4]);
            float4 bv = *reinterpret_cast<const float4*>(&Bs[k][tx * 4]);
            float a_[4] = {av.x, av.y, av.z, av.w};
            float b_[4] = {bv.x, bv.y, bv.z, bv.w};
            #pragma unroll
            for (int i = 0; i < 4; ++i)
                #pragma unroll
                for (int j = 0; j < 4; ++j)
                    acc[i][j] = fmaf(a_[i], b_[j], acc[i][j]);
        }
        __syncthreads();
    }

    // Epilogue
    #pragma unroll
    for (int i = 0; i < 4; ++i) {
        const int m = m0 + ty * 4 + i;
        const int n = n0 + tx * 4;
        float4 o;
        float* po = &o.x;
        #pragma unroll
        for (int j = 0; j < 4; ++j) {
            float v = acc[i][j];
            const int c = n + j;
            if (MODE == 1) v += bias[c];
            if (MODE == 2) v *= scale;
            if (MODE == 3) {
                const float sc = gam[c] * rsqrtf(var[c] + EPS);
                v = (v + bias[c] - mean[c]) * sc + beta[c] + resid[(long)m * N + c];
            }
            po[j] = v;
        }
        *reinterpret_cast<float4*>(&Cm[(long)m * N + n]) = o;
    }
}

extern "C" void kernel_launch(void* const* d_in, const int* in_sizes, int n_in,
                              void* d_out, int out_size) {
    (void)in_sizes; (void)n_in; (void)out_size;
    const float* detect = (const float*)d_in[0];
    const float* aim    = (const float*)d_in[1];
    const float* Wg  = (const float*)d_in[2];
    const float* bg  = (const float*)d_in[3];
    const float* Wt  = (const float*)d_in[4];
    const float* bt  = (const float*)d_in[5];
    const float* Wp  = (const float*)d_in[6];
    const float* bp  = (const float*)d_in[7];
    const float* Ww  = (const float*)d_in[8];
    const float* bw  = (const float*)d_in[9];
    const float* gw  = (const float*)d_in[10];
    const float* betw= (const float*)d_in[11];
    const float* mw  = (const float*)d_in[12];
    const float* vw  = (const float*)d_in[13];
    const float* Wq  = (const float*)d_in[14];
    const float* bq  = (const float*)d_in[15];
    const float* gq  = (const float*)d_in[16];
    const float* betq= (const float*)d_in[17];
    const float* mq  = (const float*)d_in[18];
    const float* vq  = (const float*)d_in[19];

    float* out    = (float*)d_out;
    float* out_na = out;                      // (RA, C) = non_aim
    float* out_nd = out + (long)RA * C;       // (RD, C) = non_det

    float *dx, *ax, *th, *ph, *m1, *m2, *nap, *ndp;
    cudaGetSymbolAddress((void**)&dx,  g_dx);
    cudaGetSymbolAddress((void**)&ax,  g_ax);
    cudaGetSymbolAddress((void**)&th,  g_th);
    cudaGetSymbolAddress((void**)&ph,  g_ph);
    cudaGetSymbolAddress((void**)&m1,  g_m1);
    cudaGetSymbolAddress((void**)&m2,  g_m2);
    cudaGetSymbolAddress((void**)&nap, g_nap);
    cudaGetSymbolAddress((void**)&ndp, g_ndp);

    const dim3 blk(256);
    const long sPH = (long)ND * CI, sAX = (long)NA * CI, sM = (long)CI * CI;

    // Projections (batch flattened; weights shared)
    gemm64<1,false><<<dim3(CI/64, RD/64, 1), blk>>>(detect, Wg, dx, RD, CI, C,
        0,0,0, bg, 0.f, nullptr,nullptr,nullptr,nullptr,nullptr);
    gemm64<1,false><<<dim3(CI/64, RA/64, 1), blk>>>(aim, Wg, ax, RA, CI, C,
        0,0,0, bg, 0.f, nullptr,nullptr,nullptr,nullptr,nullptr);
    gemm64<1,false><<<dim3(CI/64, RA/64, 1), blk>>>(aim, Wt, th, RA, CI, C,
        0,0,0, bt, 0.f, nullptr,nullptr,nullptr,nullptr,nullptr);
    gemm64<1,false><<<dim3(CI/64, RD/64, 1), blk>>>(detect, Wp, ph, RD, CI, C,
        0,0,0, bp, 0.f, nullptr,nullptr,nullptr,nullptr,nullptr);

    // Inner 256x256 products (associativity: avoids materializing f)
    // m1[b] = phi[b]^T @ dx[b] / ND
    gemm64<2,true><<<dim3(CI/64, CI/64, BATCH), blk>>>(ph, dx, m1, CI, CI, ND,
        sPH, sPH, sM, nullptr, 1.f/(float)ND, nullptr,nullptr,nullptr,nullptr,nullptr);
    // m2[b] = th[b]^T @ ax[b] / NA
    gemm64<2,true><<<dim3(CI/64, CI/64, BATCH), blk>>>(th, ax, m2, CI, CI, NA,
        sAX, sAX, sM, nullptr, 1.f/(float)NA, nullptr,nullptr,nullptr,nullptr,nullptr);

    // Apply: nap[b] = th[b] @ m1[b] ; ndp[b] = ph[b] @ m2[b]
    gemm64<0,false><<<dim3(CI/64, NA/64, BATCH), blk>>>(th, m1, nap, NA, CI, CI,
        sAX, sM, sAX, nullptr, 0.f, nullptr,nullptr,nullptr,nullptr,nullptr);
    gemm64<0,false><<<dim3(CI/64, ND/64, BATCH), blk>>>(ph, m2, ndp, ND, CI, CI,
        sPH, sM, sPH, nullptr, 0.f, nullptr,nullptr,nullptr,nullptr,nullptr);

    // Output convs with fused BN + residual
    gemm64<3,false><<<dim3(C/64, RA/64, 1), blk>>>(nap, Ww, out_na, RA, C, CI,
        0,0,0, bw, 0.f, gw, betw, mw, vw, aim);
    gemm64<3,false><<<dim3(C/64, RD/64, 1), blk>>>(ndp, Wq, out_nd, RD, C, CI,
        0,0,0, bq, 0.f, gq, betq, mq, vq, detect);
}